// round 1
// baseline (speedup 1.0000x reference)
#include <cuda_runtime.h>
#include <math.h>

#define F_DIM 2048
#define K_DIM 128
#define BM    128
#define BK    16
#define PAD   4          // smem row padding to break bank conflicts

// Scratch: per-feature sum of squared kernel weights s_f = sum_k W[f,k]^2
__device__ float g_s[F_DIM];

__global__ void precompute_s_kernel(const float* __restrict__ kern) {
    int f = blockIdx.x * blockDim.x + threadIdx.x;
    if (f < F_DIM) {
        const float4* row = reinterpret_cast<const float4*>(kern + (size_t)f * K_DIM);
        float s = 0.f;
#pragma unroll
        for (int i = 0; i < K_DIM / 4; ++i) {
            float4 v = row[i];
            s += v.x * v.x + v.y * v.y + v.z * v.z + v.w * v.w;
        }
        g_s[f] = s;
    }
}

__device__ __forceinline__ void fma2(unsigned long long& d, unsigned long long a,
                                     unsigned long long b) {
    asm("fma.rn.f32x2 %0, %1, %2, %0;" : "+l"(d) : "l"(a), "l"(b));
}
__device__ __forceinline__ unsigned long long pack2(float lo, float hi) {
    unsigned long long r;
    asm("mov.b64 %0, {%1, %2};" : "=l"(r) : "f"(lo), "f"(hi));
    return r;
}
__device__ __forceinline__ void unpack2(unsigned long long v, float& lo, float& hi) {
    asm("mov.b64 {%0, %1}, %2;" : "=f"(lo), "=f"(hi) : "l"(v));
}

__global__ __launch_bounds__(256, 1) void fm_main_kernel(
    const float* __restrict__ X, const float* __restrict__ W,
    const float* __restrict__ wlin, const float* __restrict__ blin,
    float* __restrict__ out) {
    __shared__ float Xs[BK][BM + PAD];      // X tile, transposed: Xs[f_local][row]
    __shared__ float Ws[BK][K_DIM + PAD];   // W tile: Ws[f_local][k]
    __shared__ float pLin[BM][4];
    __shared__ float pT[BM][4];
    __shared__ float rowLin[BM];
    __shared__ float rowT[BM];

    const int tid = threadIdx.x;
    const int tx = tid & 15;        // col group (8 cols)
    const int ty = tid >> 4;        // row group (8 rows)
    const int blockRow = blockIdx.x * BM;

    // X loader mapping: thread covers rows rA and rA+64, f-phase q (4 floats each)
    const int rA = tid >> 2;        // 0..63
    const int q  = tid & 3;         // 0..3

    float linA = 0.f, linB = 0.f, tAcc = 0.f, tBcc = 0.f;

    unsigned long long acc[8][4];   // 8 rows x 4 col-pairs, packed f32x2
#pragma unroll
    for (int i = 0; i < 8; ++i)
#pragma unroll
        for (int p = 0; p < 4; ++p) acc[i][p] = 0ull;

    const int wr = tid >> 5;        // 0..7  (W loader row)
    const int wc = tid & 31;        // 0..31 (float4 column)

    for (int f0 = 0; f0 < F_DIM; f0 += BK) {
        // ---- load X tile (and fuse the per-row linear / x^2*s reductions) ----
        {
            const int fb = f0 + q * 4;
            float4 xv = *reinterpret_cast<const float4*>(
                X + (size_t)(blockRow + rA) * F_DIM + fb);
            float4 xv2 = *reinterpret_cast<const float4*>(
                X + (size_t)(blockRow + rA + 64) * F_DIM + fb);
            const float* xa = reinterpret_cast<const float*>(&xv);
            const float* xb = reinterpret_cast<const float*>(&xv2);
#pragma unroll
            for (int e = 0; e < 4; ++e) {
                float wv = wlin[fb + e];
                float sv = g_s[fb + e];
                float a = xa[e], b = xb[e];
                linA += a * wv;  tAcc += a * a * sv;
                linB += b * wv;  tBcc += b * b * sv;
                Xs[q * 4 + e][rA]      = a;
                Xs[q * 4 + e][rA + 64] = b;
            }
        }
        // ---- load W tile ----
        {
            *reinterpret_cast<float4*>(&Ws[wr][wc * 4]) =
                *reinterpret_cast<const float4*>(W + (size_t)(f0 + wr) * K_DIM + wc * 4);
            *reinterpret_cast<float4*>(&Ws[wr + 8][wc * 4]) =
                *reinterpret_cast<const float4*>(W + (size_t)(f0 + wr + 8) * K_DIM + wc * 4);
        }
        __syncthreads();

#pragma unroll
        for (int k = 0; k < BK; ++k) {
            float xf[8];
            *reinterpret_cast<float4*>(&xf[0]) =
                *reinterpret_cast<const float4*>(&Xs[k][ty * 8]);
            *reinterpret_cast<float4*>(&xf[4]) =
                *reinterpret_cast<const float4*>(&Xs[k][ty * 8 + 4]);
            float4 w0 = *reinterpret_cast<const float4*>(&Ws[k][tx * 8]);
            float4 w1 = *reinterpret_cast<const float4*>(&Ws[k][tx * 8 + 4]);
            unsigned long long wp0 = pack2(w0.x, w0.y);
            unsigned long long wp1 = pack2(w0.z, w0.w);
            unsigned long long wp2 = pack2(w1.x, w1.y);
            unsigned long long wp3 = pack2(w1.z, w1.w);
#pragma unroll
            for (int i = 0; i < 8; ++i) {
                unsigned long long xp = pack2(xf[i], xf[i]);
                fma2(acc[i][0], xp, wp0);
                fma2(acc[i][1], xp, wp1);
                fma2(acc[i][2], xp, wp2);
                fma2(acc[i][3], xp, wp3);
            }
        }
        __syncthreads();
    }

    // ---- reduce per-row linear / t partials (4 loader threads per row) ----
    pLin[rA][q] = linA;      pT[rA][q] = tAcc;
    pLin[rA + 64][q] = linB; pT[rA + 64][q] = tBcc;
    __syncthreads();
    if (tid < BM) {
        rowLin[tid] = pLin[tid][0] + pLin[tid][1] + pLin[tid][2] + pLin[tid][3];
        rowT[tid]   = pT[tid][0] + pT[tid][1] + pT[tid][2] + pT[tid][3];
    }
    __syncthreads();

    const float bias = blin[0];
    const float invK = 1.0f / (float)K_DIM;

    // ---- epilogue: sum of squares of y over all K, then sigmoid ----
#pragma unroll
    for (int i = 0; i < 8; ++i) {
        float ssum = 0.f;
#pragma unroll
        for (int p = 0; p < 4; ++p) {
            float lo, hi;
            unpack2(acc[i][p], lo, hi);
            ssum += lo * lo + hi * hi;
        }
        // butterfly across the 16 tx-lanes (each half-warp has fixed ty)
#pragma unroll
        for (int off = 8; off >= 1; off >>= 1)
            ssum += __shfl_xor_sync(0xffffffffu, ssum, off, 16);
        if (tx == 0) {
            int lrow = ty * 8 + i;
            float cross = 0.5f * (ssum - rowT[lrow]) * invK;
            float z = rowLin[lrow] + bias + cross;
            out[blockRow + lrow] = 1.0f / (1.0f + expf(-z));
        }
    }
}

extern "C" void kernel_launch(void* const* d_in, const int* in_sizes, int n_in,
                              void* d_out, int out_size) {
    const float* x    = (const float*)d_in[0];
    const float* kern = (const float*)d_in[1];
    const float* wlin = (const float*)d_in[2];
    const float* blin = (const float*)d_in[3];
    float* out = (float*)d_out;
    const int B = out_size;  // [B,1] output

    precompute_s_kernel<<<(F_DIM + 255) / 256, 256>>>(kern);
    fm_main_kernel<<<B / BM, 256>>>(x, kern, wlin, blin, out);
}

// round 3
// speedup vs baseline: 1.0774x; 1.0774x over previous
#include <cuda_runtime.h>
#include <math.h>

#define F_DIM 2048
#define K_DIM 128
#define BM    128
#define BK    16
#define NT    (F_DIM / BK)       // 128 tiles
#define XROW  (2 * BM + 4)       // duplicated X row (floats), 16B-aligned stride
#define WROW  (K_DIM + 4)        // W row (floats), 16B-aligned stride

// dynamic smem layout (floats):
#define XS_OFF   0
#define XS_SZ    (2 * BK * XROW)            // 8320
#define WS_OFF   (XS_OFF + XS_SZ)
#define WS_SZ    (2 * BK * WROW)            // 4224
#define PLIN_OFF (WS_OFF + WS_SZ)
#define PT_OFF   (PLIN_OFF + BM * 4)
#define RLIN_OFF (PT_OFF + BM * 4)
#define RT_OFF   (RLIN_OFF + BM)
#define SMEM_FLOATS (RT_OFF + BM)
#define SMEM_BYTES  (SMEM_FLOATS * 4)       // 55296

// Scratch: g_ws[f] = { wlin[f], sum_k W[f,k]^2 }
__device__ float2 g_ws[F_DIM];

__global__ void precompute_s_kernel(const float* __restrict__ kern,
                                    const float* __restrict__ wlin) {
    int f = blockIdx.x * blockDim.x + threadIdx.x;
    if (f < F_DIM) {
        const float4* row = reinterpret_cast<const float4*>(kern + (size_t)f * K_DIM);
        float s = 0.f;
#pragma unroll
        for (int i = 0; i < K_DIM / 4; ++i) {
            float4 v = row[i];
            s += v.x * v.x + v.y * v.y + v.z * v.z + v.w * v.w;
        }
        g_ws[f] = make_float2(wlin[f], s);
    }
}

__device__ __forceinline__ void fma2(unsigned long long& d, unsigned long long a,
                                     unsigned long long b) {
    asm("fma.rn.f32x2 %0, %1, %2, %0;" : "+l"(d) : "l"(a), "l"(b));
}
__device__ __forceinline__ void unpack2(unsigned long long v, float& lo, float& hi) {
    asm("mov.b64 {%0, %1}, %2;" : "=f"(lo), "=f"(hi) : "l"(v));
}

__global__ __launch_bounds__(256, 1) void fm_main_kernel(
    const float* __restrict__ X, const float* __restrict__ W,
    const float* __restrict__ blin, float* __restrict__ out) {
    extern __shared__ float smem[];
    float* Xs = smem + XS_OFF;       // [2][BK][XROW]
    float* Ws = smem + WS_OFF;       // [2][BK][WROW]
    float* pLin = smem + PLIN_OFF;   // [BM][4]
    float* pT = smem + PT_OFF;       // [BM][4]
    float* rowLin = smem + RLIN_OFF; // [BM]
    float* rowT = smem + RT_OFF;     // [BM]

    const int tid = threadIdx.x;
    const int tx = tid & 15;        // 8-col group
    const int ty = tid >> 4;        // 8-row group
    const int blockRow = blockIdx.x * BM;

    const int rA = tid >> 2;        // 0..63
    const int q  = tid & 3;         // 0..3 (f-phase, 4 floats)
    const int wr = tid >> 5;        // 0..7
    const int wc = tid & 31;        // 0..31

    const float* xPtrA = X + (size_t)(blockRow + rA) * F_DIM + q * 4;
    const float* xPtrB = X + (size_t)(blockRow + rA + 64) * F_DIM + q * 4;
    const float* wPtr0 = W + (size_t)wr * K_DIM + wc * 4;
    const float* wPtr1 = W + (size_t)(wr + 8) * K_DIM + wc * 4;
    const float* gwPtr = reinterpret_cast<const float*>(g_ws) + q * 8;

    float linA = 0.f, linB = 0.f, tAcc = 0.f, tBcc = 0.f;

    unsigned long long acc[8][4];
#pragma unroll
    for (int i = 0; i < 8; ++i)
#pragma unroll
        for (int p = 0; p < 4; ++p) acc[i][p] = 0ull;

    float4 xva, xvb, wv0, wv1, gw0, gw1;

    // ---- prologue: tile 0 ----
    xva = *reinterpret_cast<const float4*>(xPtrA);
    xvb = *reinterpret_cast<const float4*>(xPtrB);
    wv0 = *reinterpret_cast<const float4*>(wPtr0);
    wv1 = *reinterpret_cast<const float4*>(wPtr1);
    gw0 = *reinterpret_cast<const float4*>(gwPtr);
    gw1 = *reinterpret_cast<const float4*>(gwPtr + 4);

    {
        const float* xa = reinterpret_cast<const float*>(&xva);
        const float* xb = reinterpret_cast<const float*>(&xvb);
        const float* gwa = reinterpret_cast<const float*>(&gw0);   // [w,s,w,s]
        const float* gwb = reinterpret_cast<const float*>(&gw1);
#pragma unroll
        for (int e = 0; e < 4; ++e) {
            float wv = (e < 2) ? gwa[2 * e] : gwb[2 * (e - 2)];
            float sv = (e < 2) ? gwa[2 * e + 1] : gwb[2 * (e - 2) + 1];
            float a = xa[e], b = xb[e];
            linA += a * wv;  tAcc += a * a * sv;
            linB += b * wv;  tBcc += b * b * sv;
            *reinterpret_cast<float2*>(&Xs[(q * 4 + e) * XROW + 2 * rA]) = make_float2(a, a);
            *reinterpret_cast<float2*>(&Xs[(q * 4 + e) * XROW + 2 * (rA + 64)]) = make_float2(b, b);
        }
        *reinterpret_cast<float4*>(&Ws[wr * WROW + wc * 4]) = wv0;
        *reinterpret_cast<float4*>(&Ws[(wr + 8) * WROW + wc * 4]) = wv1;
    }
    __syncthreads();

    for (int t = 0; t < NT; ++t) {
        const int nt = t + 1;
        if (nt < NT) {
            const int fOff = nt * BK;
            xva = *reinterpret_cast<const float4*>(xPtrA + fOff);
            xvb = *reinterpret_cast<const float4*>(xPtrB + fOff);
            wv0 = *reinterpret_cast<const float4*>(wPtr0 + (size_t)fOff * K_DIM);
            wv1 = *reinterpret_cast<const float4*>(wPtr1 + (size_t)fOff * K_DIM);
            gw0 = *reinterpret_cast<const float4*>(gwPtr + 2 * fOff);
            gw1 = *reinterpret_cast<const float4*>(gwPtr + 2 * fOff + 4);
        }

        // ---- compute on buffer t&1 ----
        {
            const float* xbase = Xs + (t & 1) * BK * XROW + 16 * ty;
            const float* wbase = Ws + (t & 1) * BK * WROW + 8 * tx;
#pragma unroll
            for (int k = 0; k < BK; ++k) {
                ulonglong2 x01 = *reinterpret_cast<const ulonglong2*>(xbase + k * XROW);
                ulonglong2 x23 = *reinterpret_cast<const ulonglong2*>(xbase + k * XROW + 4);
                ulonglong2 x45 = *reinterpret_cast<const ulonglong2*>(xbase + k * XROW + 8);
                ulonglong2 x67 = *reinterpret_cast<const ulonglong2*>(xbase + k * XROW + 12);
                ulonglong2 wA = *reinterpret_cast<const ulonglong2*>(wbase + k * WROW);
                ulonglong2 wB = *reinterpret_cast<const ulonglong2*>(wbase + k * WROW + 4);
                fma2(acc[0][0], x01.x, wA.x); fma2(acc[0][1], x01.x, wA.y);
                fma2(acc[0][2], x01.x, wB.x); fma2(acc[0][3], x01.x, wB.y);
                fma2(acc[1][0], x01.y, wA.x); fma2(acc[1][1], x01.y, wA.y);
                fma2(acc[1][2], x01.y, wB.x); fma2(acc[1][3], x01.y, wB.y);
                fma2(acc[2][0], x23.x, wA.x); fma2(acc[2][1], x23.x, wA.y);
                fma2(acc[2][2], x23.x, wB.x); fma2(acc[2][3], x23.x, wB.y);
                fma2(acc[3][0], x23.y, wA.x); fma2(acc[3][1], x23.y, wA.y);
                fma2(acc[3][2], x23.y, wB.x); fma2(acc[3][3], x23.y, wB.y);
                fma2(acc[4][0], x45.x, wA.x); fma2(acc[4][1], x45.x, wA.y);
                fma2(acc[4][2], x45.x, wB.x); fma2(acc[4][3], x45.x, wB.y);
                fma2(acc[5][0], x45.y, wA.x); fma2(acc[5][1], x45.y, wA.y);
                fma2(acc[5][2], x45.y, wB.x); fma2(acc[5][3], x45.y, wB.y);
                fma2(acc[6][0], x67.x, wA.x); fma2(acc[6][1], x67.x, wA.y);
                fma2(acc[6][2], x67.x, wB.x); fma2(acc[6][3], x67.x, wB.y);
                fma2(acc[7][0], x67.y, wA.x); fma2(acc[7][1], x67.y, wA.y);
                fma2(acc[7][2], x67.y, wB.x); fma2(acc[7][3], x67.y, wB.y);
            }
        }

        // ---- store next tile into buffer (t+1)&1 ----
        if (nt < NT) {
            float* xdst = Xs + (nt & 1) * BK * XROW;
            float* wdst = Ws + (nt & 1) * BK * WROW;
            const float* xa = reinterpret_cast<const float*>(&xva);
            const float* xb = reinterpret_cast<const float*>(&xvb);
            const float* gwa = reinterpret_cast<const float*>(&gw0);
            const float* gwb = reinterpret_cast<const float*>(&gw1);
#pragma unroll
            for (int e = 0; e < 4; ++e) {
                float wv = (e < 2) ? gwa[2 * e] : gwb[2 * (e - 2)];
                float sv = (e < 2) ? gwa[2 * e + 1] : gwb[2 * (e - 2) + 1];
                float a = xa[e], b = xb[e];
                linA += a * wv;  tAcc += a * a * sv;
                linB += b * wv;  tBcc += b * b * sv;
                *reinterpret_cast<float2*>(&xdst[(q * 4 + e) * XROW + 2 * rA]) = make_float2(a, a);
                *reinterpret_cast<float2*>(&xdst[(q * 4 + e) * XROW + 2 * (rA + 64)]) = make_float2(b, b);
            }
            *reinterpret_cast<float4*>(&wdst[wr * WROW + wc * 4]) = wv0;
            *reinterpret_cast<float4*>(&wdst[(wr + 8) * WROW + wc * 4]) = wv1;
        }
        __syncthreads();
    }

    // ---- reduce per-row linear / t partials ----
    pLin[rA * 4 + q] = linA;        pT[rA * 4 + q] = tAcc;
    pLin[(rA + 64) * 4 + q] = linB; pT[(rA + 64) * 4 + q] = tBcc;
    __syncthreads();
    if (tid < BM) {
        rowLin[tid] = pLin[tid * 4] + pLin[tid * 4 + 1] + pLin[tid * 4 + 2] + pLin[tid * 4 + 3];
        rowT[tid]   = pT[tid * 4] + pT[tid * 4 + 1] + pT[tid * 4 + 2] + pT[tid * 4 + 3];
    }
    __syncthreads();

    const float bias = blin[0];
    const float invK = 1.0f / (float)K_DIM;

#pragma unroll
    for (int i = 0; i < 8; ++i) {
        float ssum = 0.f;
#pragma unroll
        for (int p = 0; p < 4; ++p) {
            float lo, hi;
            unpack2(acc[i][p], lo, hi);
            ssum += lo * lo + hi * hi;
        }
#pragma unroll
        for (int off = 8; off >= 1; off >>= 1)
            ssum += __shfl_xor_sync(0xffffffffu, ssum, off, 16);
        if (tx == 0) {
            int lrow = ty * 8 + i;
            float cross = 0.5f * (ssum - rowT[lrow]) * invK;
            float z = rowLin[lrow] + bias + cross;
            out[blockRow + lrow] = 1.0f / (1.0f + expf(-z));
        }
    }
}

extern "C" void kernel_launch(void* const* d_in, const int* in_sizes, int n_in,
                              void* d_out, int out_size) {
    const float* x    = (const float*)d_in[0];
    const float* kern = (const float*)d_in[1];
    const float* wlin = (const float*)d_in[2];
    const float* blin = (const float*)d_in[3];
    float* out = (float*)d_out;
    const int B = out_size;

    cudaFuncSetAttribute(fm_main_kernel,
                         cudaFuncAttributeMaxDynamicSharedMemorySize, SMEM_BYTES);
    precompute_s_kernel<<<(F_DIM + 255) / 256, 256>>>(kern, wlin);
    fm_main_kernel<<<B / BM, 256, SMEM_BYTES>>>(x, kern, blin, out);
}

// round 5
// speedup vs baseline: 1.6235x; 1.5068x over previous
#include <cuda_runtime.h>
#include <cstdint>
#include <math.h>

#define F_DIM 2048
#define K_DIM 128
#define BM    128
#define BK    32
#define NT    (F_DIM / BK)     // 64 k-tiles
#define XSTR  36               // Xs row stride (floats): 36 % 32 == 4 -> conflict-free frags
#define WSTR  132              // Ws row stride (floats)

// dynamic smem layout (floats)
#define SM_X      0
#define SM_X_SZ   (2 * BM * XSTR)          // 9216
#define SM_W      (SM_X + SM_X_SZ)
#define SM_W_SZ   (2 * BK * WSTR)          // 8448
#define SM_PS     (SM_W + SM_W_SZ)         // [128][2] partial sum-of-squares
#define SM_RLIN   (SM_PS + 2 * BM)
#define SM_RT     (SM_RLIN + BM)
#define SMEM_FLOATS (SM_RT + BM)
#define SMEM_BYTES  (SMEM_FLOATS * 4)      // 72704

__device__ float  g_wcvt[F_DIM * K_DIM];   // tf32-rounded W, [f][n]
__device__ float2 g_ws[F_DIM];             // {wlin[f], sum_k W[f,k]^2} exact fp32

__device__ __forceinline__ float to_tf32(float x) {
    uint32_t u;
    asm("cvt.rna.tf32.f32 %0, %1;" : "=r"(u) : "f"(x));
    return __uint_as_float(u);
}

__device__ __forceinline__ void mma_tf32(float* d, const uint32_t* a,
                                         uint32_t b0, uint32_t b1) {
    asm volatile(
        "mma.sync.aligned.m16n8k8.row.col.f32.tf32.tf32.f32 "
        "{%0,%1,%2,%3}, {%4,%5,%6,%7}, {%8,%9}, {%0,%1,%2,%3};"
        : "+f"(d[0]), "+f"(d[1]), "+f"(d[2]), "+f"(d[3])
        : "r"(a[0]), "r"(a[1]), "r"(a[2]), "r"(a[3]), "r"(b0), "r"(b1));
}

// ---------------- precompute ----------------
__global__ void precompute_s_kernel(const float* __restrict__ kern,
                                    const float* __restrict__ wlin) {
    int f = blockIdx.x * blockDim.x + threadIdx.x;
    if (f < F_DIM) {
        const float4* row = reinterpret_cast<const float4*>(kern + (size_t)f * K_DIM);
        float s = 0.f;
#pragma unroll
        for (int i = 0; i < K_DIM / 4; ++i) {
            float4 v = row[i];
            s += v.x * v.x + v.y * v.y + v.z * v.z + v.w * v.w;
        }
        g_ws[f] = make_float2(wlin[f], s);
    }
}

__global__ void wcvt_kernel(const float* __restrict__ W) {
    int i = blockIdx.x * blockDim.x + threadIdx.x;   // float4 index
    float4 v = reinterpret_cast<const float4*>(W)[i];
    v.x = to_tf32(v.x); v.y = to_tf32(v.y); v.z = to_tf32(v.z); v.w = to_tf32(v.w);
    reinterpret_cast<float4*>(g_wcvt)[i] = v;
}

// ---------------- main kernel ----------------
__global__ __launch_bounds__(256, 1) void fm_mma_kernel(
    const float* __restrict__ X, const float* __restrict__ blin,
    float* __restrict__ out) {
    extern __shared__ float smem[];
    float* Xs  = smem + SM_X;
    float* Ws  = smem + SM_W;
    float* pS  = smem + SM_PS;
    float* rowLin = smem + SM_RLIN;
    float* rowT   = smem + SM_RT;

    const int tid  = threadIdx.x;
    const int lane = tid & 31;
    const int wid  = tid >> 5;
    const int wm   = wid >> 1;          // 0..3 (M slice of 32)
    const int wn   = wid & 1;           // 0..1 (N slice of 64)
    const int blockRow = blockIdx.x * BM;

    // loaders
    const int r  = tid >> 1;            // X row 0..127
    const int h  = tid & 1;             // k half (16 floats)
    const int kr = tid >> 3;            // W f-row 0..31
    const int sg = tid & 7;             // W n segment (16 floats)

    const float* xrow = X + (size_t)(blockRow + r) * F_DIM + h * 16;
    const float* gwsP = reinterpret_cast<const float*>(g_ws) + h * 32;

    float linP = 0.f, tP = 0.f;
    float acc[2][8][4];
#pragma unroll
    for (int i = 0; i < 2; ++i)
#pragma unroll
        for (int j = 0; j < 8; ++j)
#pragma unroll
            for (int e = 0; e < 4; ++e) acc[i][j][e] = 0.f;

    float4 xv[4], wv[4];

    // ---- prologue: load tile 0, accumulate lin/t, store to buf 0 ----
#pragma unroll
    for (int j = 0; j < 4; ++j) {
        xv[j] = *reinterpret_cast<const float4*>(xrow + j * 4);
        float4 g0 = *reinterpret_cast<const float4*>(gwsP + j * 8);
        float4 g1 = *reinterpret_cast<const float4*>(gwsP + j * 8 + 4);
        linP += xv[j].x * g0.x + xv[j].y * g0.z + xv[j].z * g1.x + xv[j].w * g1.z;
        tP   += xv[j].x * xv[j].x * g0.y + xv[j].y * xv[j].y * g0.w
              + xv[j].z * xv[j].z * g1.y + xv[j].w * xv[j].w * g1.w;
        wv[j] = *reinterpret_cast<const float4*>(
            g_wcvt + (size_t)kr * K_DIM + sg * 16 + j * 4);
    }
#pragma unroll
    for (int j = 0; j < 4; ++j) {
        float4 c = make_float4(to_tf32(xv[j].x), to_tf32(xv[j].y),
                               to_tf32(xv[j].z), to_tf32(xv[j].w));
        *reinterpret_cast<float4*>(&Xs[r * XSTR + h * 16 + j * 4]) = c;
        *reinterpret_cast<float4*>(&Ws[kr * WSTR + sg * 16 + j * 4]) = wv[j];
    }
    __syncthreads();

    for (int t = 0; t < NT; ++t) {
        const int nt = t + 1;
        if (nt < NT) {
            const int f0 = nt * BK;
            const float* gp = gwsP + f0 * 2;
#pragma unroll
            for (int j = 0; j < 4; ++j) {
                xv[j] = *reinterpret_cast<const float4*>(xrow + f0 + j * 4);
                float4 g0 = *reinterpret_cast<const float4*>(gp + j * 8);
                float4 g1 = *reinterpret_cast<const float4*>(gp + j * 8 + 4);
                linP += xv[j].x * g0.x + xv[j].y * g0.z + xv[j].z * g1.x + xv[j].w * g1.z;
                tP   += xv[j].x * xv[j].x * g0.y + xv[j].y * xv[j].y * g0.w
                      + xv[j].z * xv[j].z * g1.y + xv[j].w * xv[j].w * g1.w;
                wv[j] = *reinterpret_cast<const float4*>(
                    g_wcvt + (size_t)(f0 + kr) * K_DIM + sg * 16 + j * 4);
            }
        }

        // ---- compute on buffer t&1 ----
        {
            const float* xb = Xs + (t & 1) * BM * XSTR + (wm * 32 + (lane >> 2)) * XSTR;
            const float* wb = Ws + (t & 1) * BK * WSTR + wn * 64 + (lane >> 2);
            const int c0 = lane & 3;
#pragma unroll
            for (int ks = 0; ks < 4; ++ks) {
                uint32_t a[2][4];
#pragma unroll
                for (int i = 0; i < 2; ++i) {
                    const float* xi = xb + i * 16 * XSTR + ks * 8;
                    a[i][0] = __float_as_uint(xi[c0]);
                    a[i][1] = __float_as_uint(xi[8 * XSTR + c0]);
                    a[i][2] = __float_as_uint(xi[c0 + 4]);
                    a[i][3] = __float_as_uint(xi[8 * XSTR + c0 + 4]);
                }
                const float* wk = wb + (ks * 8 + c0) * WSTR;
#pragma unroll
                for (int j = 0; j < 8; ++j) {
                    uint32_t b0 = __float_as_uint(wk[j * 8]);
                    uint32_t b1 = __float_as_uint(wk[4 * WSTR + j * 8]);
                    mma_tf32(acc[0][j], a[0], b0, b1);
                    mma_tf32(acc[1][j], a[1], b0, b1);
                }
            }
        }

        // ---- store next tile to buffer nt&1 ----
        if (nt < NT) {
            float* xd = Xs + (nt & 1) * BM * XSTR;
            float* wd = Ws + (nt & 1) * BK * WSTR;
#pragma unroll
            for (int j = 0; j < 4; ++j) {
                float4 c = make_float4(to_tf32(xv[j].x), to_tf32(xv[j].y),
                                       to_tf32(xv[j].z), to_tf32(xv[j].w));
                *reinterpret_cast<float4*>(&xd[r * XSTR + h * 16 + j * 4]) = c;
                *reinterpret_cast<float4*>(&wd[kr * WSTR + sg * 16 + j * 4]) = wv[j];
            }
        }
        __syncthreads();
    }

    // ---- per-row lin/t (pair of loader threads per row) ----
    {
        float linO = __shfl_xor_sync(0xffffffffu, linP, 1);
        float tO   = __shfl_xor_sync(0xffffffffu, tP, 1);
        if (h == 0) { rowLin[r] = linP + linO; rowT[r] = tP + tO; }
    }

    // ---- epilogue: per-warp sum of squares over its 64 cols ----
#pragma unroll
    for (int i = 0; i < 2; ++i) {
        float s0 = 0.f, s1 = 0.f;
#pragma unroll
        for (int j = 0; j < 8; ++j) {
            s0 += acc[i][j][0] * acc[i][j][0] + acc[i][j][1] * acc[i][j][1];
            s1 += acc[i][j][2] * acc[i][j][2] + acc[i][j][3] * acc[i][j][3];
        }
        s0 += __shfl_xor_sync(0xffffffffu, s0, 1);
        s0 += __shfl_xor_sync(0xffffffffu, s0, 2);
        s1 += __shfl_xor_sync(0xffffffffu, s1, 1);
        s1 += __shfl_xor_sync(0xffffffffu, s1, 2);
        if ((lane & 3) == 0) {
            int row0 = wm * 32 + i * 16 + (lane >> 2);
            pS[row0 * 2 + wn] = s0;
            pS[(row0 + 8) * 2 + wn] = s1;
        }
    }
    __syncthreads();

    if (tid < BM) {
        float ssum = pS[tid * 2] + pS[tid * 2 + 1];
        float cross = 0.5f * (ssum - rowT[tid]) * (1.0f / (float)K_DIM);
        float z = rowLin[tid] + blin[0] + cross;
        out[blockRow + tid] = 1.0f / (1.0f + expf(-z));
    }
}

extern "C" void kernel_launch(void* const* d_in, const int* in_sizes, int n_in,
                              void* d_out, int out_size) {
    const float* x    = (const float*)d_in[0];
    const float* kern = (const float*)d_in[1];
    const float* wlin = (const float*)d_in[2];
    const float* blin = (const float*)d_in[3];
    float* out = (float*)d_out;
    const int B = out_size;

    cudaFuncSetAttribute(fm_mma_kernel,
                         cudaFuncAttributeMaxDynamicSharedMemorySize, SMEM_BYTES);
    precompute_s_kernel<<<(F_DIM + 255) / 256, 256>>>(kern, wlin);
    wcvt_kernel<<<(F_DIM * K_DIM / 4) / 256, 256>>>(kern);
    fm_mma_kernel<<<B / BM, 256, SMEM_BYTES>>>(x, blin, out);
}

// round 6
// speedup vs baseline: 2.1053x; 1.2968x over previous
#include <cuda_runtime.h>
#include <cstdint>
#include <math.h>

#define F_DIM 2048
#define K_DIM 128
#define BM    128
#define BK    32
#define NT    (F_DIM / BK)     // 64 k-tiles

// ---- smem layout ----
// A frag buffers: float4 units, 32 blocks/buffer, 33 f4 per block (pad)
#define A_BLK_F4   33
#define A_BUF_F4   (32 * A_BLK_F4)          // 1056 f4 = 16896 B
// B pair buffers: float2 units, 16 blocks/buffer, 132 f2 per block (pad)
#define B_BLK_F2   132
#define B_BUF_F2   (16 * B_BLK_F2)          // 2112 f2 = 16896 B
#define SM_A_BYTES (2 * A_BUF_F4 * 16)      // 33792
#define SM_B_OFF   SM_A_BYTES
#define SM_B_BYTES (2 * B_BUF_F2 * 8)       // 33792
#define SM_PS_OFF  (SM_B_OFF + SM_B_BYTES)  // float[128][2]
#define SM_RLIN_OFF (SM_PS_OFF + 1024)
#define SM_RT_OFF   (SM_RLIN_OFF + 512)
#define SMEM_BYTES  (SM_RT_OFF + 512)       // 69632

__device__ float  g_wcvt[F_DIM * K_DIM];   // tf32-rounded W, [f][n]
__device__ float2 g_ws[F_DIM];             // {wlin[f], exact sum_k W[f,k]^2}

__device__ __forceinline__ float to_tf32(float x) {
    uint32_t u;
    asm("cvt.rna.tf32.f32 %0, %1;" : "=r"(u) : "f"(x));
    return __uint_as_float(u);
}
__device__ __forceinline__ void mma_tf32(float* d, uint32_t a0, uint32_t a1,
                                         uint32_t a2, uint32_t a3,
                                         uint32_t b0, uint32_t b1) {
    asm volatile(
        "mma.sync.aligned.m16n8k8.row.col.f32.tf32.tf32.f32 "
        "{%0,%1,%2,%3}, {%4,%5,%6,%7}, {%8,%9}, {%0,%1,%2,%3};"
        : "+f"(d[0]), "+f"(d[1]), "+f"(d[2]), "+f"(d[3])
        : "r"(a0), "r"(a1), "r"(a2), "r"(a3), "r"(b0), "r"(b1));
}

// ---------------- fused prologue: s_f, wlin pack, tf32 W convert ----------------
__global__ void prep_kernel(const float* __restrict__ kern,
                            const float* __restrict__ wlin) {
    const int gw = (blockIdx.x * blockDim.x + threadIdx.x) >> 5;  // 0..511
    const int lane = threadIdx.x & 31;
#pragma unroll
    for (int rr = 0; rr < 4; ++rr) {
        const int f = gw * 4 + rr;
        float4 v = *reinterpret_cast<const float4*>(kern + (size_t)f * K_DIM + lane * 4);
        float s = v.x * v.x + v.y * v.y + v.z * v.z + v.w * v.w;
#pragma unroll
        for (int off = 16; off >= 1; off >>= 1)
            s += __shfl_xor_sync(0xffffffffu, s, off);
        float4 c = make_float4(to_tf32(v.x), to_tf32(v.y), to_tf32(v.z), to_tf32(v.w));
        *reinterpret_cast<float4*>(g_wcvt + (size_t)f * K_DIM + lane * 4) = c;
        if (lane == 0) g_ws[f] = make_float2(wlin[f], s);
    }
}

// ---------------- main kernel ----------------
__global__ __launch_bounds__(256, 1) void fm_mma_kernel(
    const float* __restrict__ X, const float* __restrict__ blin,
    float* __restrict__ out) {
    extern __shared__ char smem[];
    float4* Af  = reinterpret_cast<float4*>(smem);
    float2* Bf  = reinterpret_cast<float2*>(smem + SM_B_OFF);
    float*  pS  = reinterpret_cast<float*>(smem + SM_PS_OFF);
    float*  rowLin = reinterpret_cast<float*>(smem + SM_RLIN_OFF);
    float*  rowT   = reinterpret_cast<float*>(smem + SM_RT_OFF);

    const int tid  = threadIdx.x;
    const int lane = tid & 31;
    const int wid  = tid >> 5;
    const int wm   = wid >> 1;              // 0..3
    const int wn   = wid & 1;               // 0..1
    const int blockRow = blockIdx.x * BM;

    // A loader: rid covers row pair (rlow, rlow+8), cseg = 8 cols
    const int rid  = tid >> 2;              // 0..63
    const int cseg = tid & 3;               // 0..3
    const int rlow = (rid & 7) | ((rid >> 3) << 4);
    const int wm2i = rid >> 3;              // 0..7  (frag block row-group)
    // B loader: rows (f0+ksl*8+c0l, +4), 8 cols at nseg2*8
    const int ksl   = tid >> 6;             // 0..3
    const int nseg2 = (tid >> 2) & 15;      // 0..15
    const int c0l   = tid & 3;              // 0..3

    const float* xLo = X + (size_t)(blockRow + rlow) * F_DIM + cseg * 8;
    const float* xHi = xLo + 8 * F_DIM;
    const float* wLo = g_wcvt + (size_t)(ksl * 8 + c0l) * K_DIM + nseg2 * 8;
    const float* wHi = wLo + 4 * K_DIM;
    const float4* wsP = reinterpret_cast<const float4*>(g_ws) + cseg * 4;

    float linLo = 0.f, linHi = 0.f, tLo = 0.f, tHi = 0.f;
    float acc[2][8][4];
#pragma unroll
    for (int i = 0; i < 2; ++i)
#pragma unroll
        for (int j = 0; j < 8; ++j)
#pragma unroll
            for (int e = 0; e < 4; ++e) acc[i][j][e] = 0.f;

    float4 xl[2], xh[2], wl[2], wh[2];

    // stage tile f0 into registers + side reductions
    auto ldg_tile = [&](int f0) {
        xl[0] = *reinterpret_cast<const float4*>(xLo + f0);
        xl[1] = *reinterpret_cast<const float4*>(xLo + f0 + 4);
        xh[0] = *reinterpret_cast<const float4*>(xHi + f0);
        xh[1] = *reinterpret_cast<const float4*>(xHi + f0 + 4);
        wl[0] = *reinterpret_cast<const float4*>(wLo + (size_t)f0 * K_DIM);
        wl[1] = *reinterpret_cast<const float4*>(wLo + (size_t)f0 * K_DIM + 4);
        wh[0] = *reinterpret_cast<const float4*>(wHi + (size_t)f0 * K_DIM);
        wh[1] = *reinterpret_cast<const float4*>(wHi + (size_t)f0 * K_DIM + 4);
        const float4* wp = wsP + f0 / 2;
        const float* lo = reinterpret_cast<const float*>(&xl[0]);
        const float* hi = reinterpret_cast<const float*>(&xh[0]);
#pragma unroll
        for (int u = 0; u < 4; ++u) {
            float4 g = __ldg(wp + u);             // {w,s} for f = cseg*8+2u, +1
            float a0 = lo[2 * u], a1 = lo[2 * u + 1];
            float b0 = hi[2 * u], b1 = hi[2 * u + 1];
            linLo += a0 * g.x + a1 * g.z;  tLo += a0 * a0 * g.y + a1 * a1 * g.w;
            linHi += b0 * g.x + b1 * g.z;  tHi += b0 * b0 * g.y + b1 * b1 * g.w;
        }
    };
    auto sts_tile = [&](int buf) {
        // A frag-order: float4 {lo[e], hi[e], lo[e+4], hi[e+4]} at block (wm2i*4+cseg)
        float4* ad = Af + buf * A_BUF_F4 + (wm2i * 4 + cseg) * A_BLK_F4;
        const float* lo = reinterpret_cast<const float*>(&xl[0]);
        const float* hi = reinterpret_cast<const float*>(&xh[0]);
#pragma unroll
        for (int e = 0; e < 4; ++e) {
            int fl = (rlow & 7) * 4 + e;
            ad[fl] = make_float4(to_tf32(lo[e]), to_tf32(hi[e]),
                                 to_tf32(lo[e + 4]), to_tf32(hi[e + 4]));
        }
        // B pair-order: float4 {lo[2e'],hi[2e'],lo[2e'+1],hi[2e'+1]}
        float4* bd = reinterpret_cast<float4*>(Bf + buf * B_BUF_F2) +
                     (ksl * 4 + c0l) * (B_BLK_F2 / 2) + nseg2 * 4;
        const float* bl = reinterpret_cast<const float*>(&wl[0]);
        const float* bh = reinterpret_cast<const float*>(&wh[0]);
#pragma unroll
        for (int e = 0; e < 4; ++e)
            bd[e] = make_float4(bl[2 * e], bh[2 * e], bl[2 * e + 1], bh[2 * e + 1]);
    };

    ldg_tile(0);
    sts_tile(0);
    __syncthreads();

    for (int t = 0; t < NT; ++t) {
        const int nt = t + 1;
        if (nt < NT) ldg_tile(nt * BK);

        // ---- compute tile t from buffer t&1 ----
        {
            const float4* ab = Af + (t & 1) * A_BUF_F4 + (wm * 2) * 4 * A_BLK_F4 + lane;
            const float2* bb = Bf + (t & 1) * B_BUF_F2 +
                               (lane & 3) * B_BLK_F2 + wn * 64 + (lane >> 2);
#pragma unroll
            for (int ks = 0; ks < 4; ++ks) {
                float4 a0 = ab[ks * A_BLK_F4];
                float4 a1 = ab[(4 + ks) * A_BLK_F4];
                const float2* bk = bb + ks * 4 * B_BLK_F2;
#pragma unroll
                for (int j = 0; j < 8; ++j) {
                    float2 b = bk[j * 8];
                    mma_tf32(acc[0][j],
                             __float_as_uint(a0.x), __float_as_uint(a0.y),
                             __float_as_uint(a0.z), __float_as_uint(a0.w),
                             __float_as_uint(b.x), __float_as_uint(b.y));
                    mma_tf32(acc[1][j],
                             __float_as_uint(a1.x), __float_as_uint(a1.y),
                             __float_as_uint(a1.z), __float_as_uint(a1.w),
                             __float_as_uint(b.x), __float_as_uint(b.y));
                }
            }
        }

        if (nt < NT) sts_tile(nt & 1);
        __syncthreads();
    }

    // ---- per-row lin/t reduce (4 cseg lanes per row pair) ----
    {
        linLo += __shfl_xor_sync(0xffffffffu, linLo, 1);
        linLo += __shfl_xor_sync(0xffffffffu, linLo, 2);
        linHi += __shfl_xor_sync(0xffffffffu, linHi, 1);
        linHi += __shfl_xor_sync(0xffffffffu, linHi, 2);
        tLo += __shfl_xor_sync(0xffffffffu, tLo, 1);
        tLo += __shfl_xor_sync(0xffffffffu, tLo, 2);
        tHi += __shfl_xor_sync(0xffffffffu, tHi, 1);
        tHi += __shfl_xor_sync(0xffffffffu, tHi, 2);
        if (cseg == 0) {
            rowLin[rlow] = linLo;  rowT[rlow] = tLo;
            rowLin[rlow + 8] = linHi;  rowT[rlow + 8] = tHi;
        }
    }

    // ---- epilogue: sum of squares ----
#pragma unroll
    for (int i = 0; i < 2; ++i) {
        float sLo = 0.f, sHi = 0.f;
#pragma unroll
        for (int j = 0; j < 8; ++j) {
            sLo += acc[i][j][0] * acc[i][j][0] + acc[i][j][1] * acc[i][j][1];
            sHi += acc[i][j][2] * acc[i][j][2] + acc[i][j][3] * acc[i][j][3];
        }
        sLo += __shfl_xor_sync(0xffffffffu, sLo, 1);
        sLo += __shfl_xor_sync(0xffffffffu, sLo, 2);
        sHi += __shfl_xor_sync(0xffffffffu, sHi, 1);
        sHi += __shfl_xor_sync(0xffffffffu, sHi, 2);
        if ((lane & 3) == 0) {
            int rowL = wm * 32 + i * 16 + (lane >> 2);
            pS[rowL * 2 + wn] = sLo;
            pS[(rowL + 8) * 2 + wn] = sHi;
        }
    }
    __syncthreads();

    if (tid < BM) {
        float ssum = pS[tid * 2] + pS[tid * 2 + 1];
        float cross = 0.5f * (ssum - rowT[tid]) * (1.0f / (float)K_DIM);
        float z = rowLin[tid] + blin[0] + cross;
        out[blockRow + tid] = 1.0f / (1.0f + expf(-z));
    }
}

extern "C" void kernel_launch(void* const* d_in, const int* in_sizes, int n_in,
                              void* d_out, int out_size) {
    const float* x    = (const float*)d_in[0];
    const float* kern = (const float*)d_in[1];
    const float* wlin = (const float*)d_in[2];
    const float* blin = (const float*)d_in[3];
    float* out = (float*)d_out;
    const int B = out_size;

    cudaFuncSetAttribute(fm_mma_kernel,
                         cudaFuncAttributeMaxDynamicSharedMemorySize, SMEM_BYTES);
    prep_kernel<<<64, 256>>>(kern, wlin);
    fm_mma_kernel<<<B / BM, 256, SMEM_BYTES>>>(x, blin, out);
}

// round 8
// speedup vs baseline: 2.4965x; 1.1858x over previous
#include <cuda_runtime.h>
#include <cstdint>
#include <math.h>

#define F_DIM 2048
#define K_DIM 128
#define BM    128
#define BK    32
#define NT    (F_DIM / BK)     // 64 k-tiles

// ---- smem layout (proven conflict-free in R6) ----
#define A_BLK_F4   33
#define A_BUF_F4   (32 * A_BLK_F4)
#define B_BLK_F2   132
#define B_BUF_F2   (16 * B_BLK_F2)
#define SM_A_BYTES (2 * A_BUF_F4 * 16)        // 33792
#define SM_B_OFF   SM_A_BYTES
#define SM_B_BYTES (2 * B_BUF_F2 * 8)         // 33792
#define SM_PS_OFF  (SM_B_OFF + SM_B_BYTES)    // float[128][4]
#define SM_RLIN_OFF (SM_PS_OFF + 2048)
#define SM_RT_OFF   (SM_RLIN_OFF + 512)
#define SMEM_BYTES  (SM_RT_OFF + 512)         // 71680

__device__ float  g_wcvt[F_DIM * K_DIM];   // tf32-rounded W, [f][n]
__device__ float2 g_ws[F_DIM];             // {wlin[f], exact sum_k W[f,k]^2}

__device__ __forceinline__ float to_tf32(float x) {
    uint32_t u;
    asm("cvt.rna.tf32.f32 %0, %1;" : "=r"(u) : "f"(x));
    return __uint_as_float(u);
}
__device__ __forceinline__ void mma_tf32(float* d, uint32_t a0, uint32_t a1,
                                         uint32_t a2, uint32_t a3,
                                         uint32_t b0, uint32_t b1) {
    asm volatile(
        "mma.sync.aligned.m16n8k8.row.col.f32.tf32.tf32.f32 "
        "{%0,%1,%2,%3}, {%4,%5,%6,%7}, {%8,%9}, {%0,%1,%2,%3};"
        : "+f"(d[0]), "+f"(d[1]), "+f"(d[2]), "+f"(d[3])
        : "r"(a0), "r"(a1), "r"(a2), "r"(a3), "r"(b0), "r"(b1));
}

// ---------------- fused prologue ----------------
__global__ void prep_kernel(const float* __restrict__ kern,
                            const float* __restrict__ wlin) {
    const int gw = (blockIdx.x * blockDim.x + threadIdx.x) >> 5;  // 0..511
    const int lane = threadIdx.x & 31;
#pragma unroll
    for (int rr = 0; rr < 4; ++rr) {
        const int f = gw * 4 + rr;
        float4 v = *reinterpret_cast<const float4*>(kern + (size_t)f * K_DIM + lane * 4);
        float s = v.x * v.x + v.y * v.y + v.z * v.z + v.w * v.w;
#pragma unroll
        for (int off = 16; off >= 1; off >>= 1)
            s += __shfl_xor_sync(0xffffffffu, s, off);
        float4 c = make_float4(to_tf32(v.x), to_tf32(v.y), to_tf32(v.z), to_tf32(v.w));
        *reinterpret_cast<float4*>(g_wcvt + (size_t)f * K_DIM + lane * 4) = c;
        if (lane == 0) g_ws[f] = make_float2(wlin[f], s);
    }
}

// ---------------- main kernel: 512 threads, 16 warps ----------------
__global__ __launch_bounds__(512, 1) void fm_mma_kernel(
    const float* __restrict__ X, const float* __restrict__ blin,
    float* __restrict__ out) {
    extern __shared__ char smem[];
    float4* Af  = reinterpret_cast<float4*>(smem);
    float2* Bf  = reinterpret_cast<float2*>(smem + SM_B_OFF);
    float*  pS  = reinterpret_cast<float*>(smem + SM_PS_OFF);
    float*  rowLin = reinterpret_cast<float*>(smem + SM_RLIN_OFF);
    float*  rowT   = reinterpret_cast<float*>(smem + SM_RT_OFF);

    const int tid  = threadIdx.x;
    const int lane = tid & 31;
    const int wid  = tid >> 5;
    const int wm   = wid >> 2;              // 0..3 (32-row slice)
    const int wn   = wid & 3;               // 0..3 (32-col slice)
    const int blockRow = blockIdx.x * BM;
    const bool isA = (tid < 256);           // warps 0-7: A loaders; 8-15: B loaders

    // A loader mapping (tid 0..255)
    const int rid  = tid >> 2;              // 0..63 (row pairs)
    const int cseg = tid & 3;               // 8-k segment
    const int rlow = (rid & 7) | ((rid >> 3) << 4);
    const int wm2i = rid >> 3;              // 16-row group 0..7
    // B loader mapping (tid 256..511)
    const int t2    = tid & 255;
    const int ksl   = t2 >> 6;              // 0..3
    const int nseg2 = (t2 >> 2) & 15;       // 0..15
    const int c0l   = t2 & 3;               // 0..3

    const float* xLo = X + (size_t)(blockRow + rlow) * F_DIM + cseg * 8;
    const float* xHi = xLo + 8 * F_DIM;
    const float* wLo = g_wcvt + (size_t)(ksl * 8 + c0l) * K_DIM + nseg2 * 8;
    const float* wHi = wLo + 4 * K_DIM;
    const float4* wsP = reinterpret_cast<const float4*>(g_ws) + cseg * 4;

    float linLo = 0.f, linHi = 0.f, tLo = 0.f, tHi = 0.f;
    float acc[2][4][4];
#pragma unroll
    for (int i = 0; i < 2; ++i)
#pragma unroll
        for (int j = 0; j < 4; ++j)
#pragma unroll
            for (int e = 0; e < 4; ++e) acc[i][j][e] = 0.f;

    // staged tile — MUST be a contiguous array (code indexes across elements)
    float4 st[4];

    auto ldg_tile = [&](int f0) {
        if (isA) {
            st[0] = *reinterpret_cast<const float4*>(xLo + f0);
            st[1] = *reinterpret_cast<const float4*>(xLo + f0 + 4);
            st[2] = *reinterpret_cast<const float4*>(xHi + f0);
            st[3] = *reinterpret_cast<const float4*>(xHi + f0 + 4);
            const float4* wp = wsP + f0 / 2;
            const float* lo = reinterpret_cast<const float*>(&st[0]);  // 8 floats st[0..1]
            const float* hi = reinterpret_cast<const float*>(&st[2]);  // 8 floats st[2..3]
#pragma unroll
            for (int u = 0; u < 4; ++u) {
                float4 g = __ldg(wp + u);
                float a0 = lo[2 * u], a1 = lo[2 * u + 1];
                float b0 = hi[2 * u], b1 = hi[2 * u + 1];
                linLo += a0 * g.x + a1 * g.z;  tLo += a0 * a0 * g.y + a1 * a1 * g.w;
                linHi += b0 * g.x + b1 * g.z;  tHi += b0 * b0 * g.y + b1 * b1 * g.w;
            }
        } else {
            st[0] = *reinterpret_cast<const float4*>(wLo + (size_t)f0 * K_DIM);
            st[1] = *reinterpret_cast<const float4*>(wLo + (size_t)f0 * K_DIM + 4);
            st[2] = *reinterpret_cast<const float4*>(wHi + (size_t)f0 * K_DIM);
            st[3] = *reinterpret_cast<const float4*>(wHi + (size_t)f0 * K_DIM + 4);
        }
    };
    auto sts_tile = [&](int buf) {
        if (isA) {
            float4* ad = Af + buf * A_BUF_F4 + (wm2i * 4 + cseg) * A_BLK_F4;
            const float* lo = reinterpret_cast<const float*>(&st[0]);
            const float* hi = reinterpret_cast<const float*>(&st[2]);
#pragma unroll
            for (int e = 0; e < 4; ++e) {
                int fl = (rlow & 7) * 4 + e;
                ad[fl] = make_float4(lo[e], hi[e], lo[e + 4], hi[e + 4]);
            }
        } else {
            float4* bd = reinterpret_cast<float4*>(Bf + buf * B_BUF_F2) +
                         (ksl * 4 + c0l) * (B_BLK_F2 / 2) + nseg2 * 4;
            const float* bl = reinterpret_cast<const float*>(&st[0]);
            const float* bh = reinterpret_cast<const float*>(&st[2]);
#pragma unroll
            for (int e = 0; e < 4; ++e)
                bd[e] = make_float4(bl[2 * e], bh[2 * e], bl[2 * e + 1], bh[2 * e + 1]);
        }
    };

    ldg_tile(0);
    sts_tile(0);
    __syncthreads();

    for (int t = 0; t < NT; ++t) {
        const int nt = t + 1;
        if (nt < NT) ldg_tile(nt * BK);

        // ---- compute tile t from buffer t&1 ----
        {
            const float4* ab = Af + (t & 1) * A_BUF_F4 + (wm * 2) * 4 * A_BLK_F4 + lane;
            const float2* bb = Bf + (t & 1) * B_BUF_F2 +
                               (lane & 3) * B_BLK_F2 + wn * 32 + (lane >> 2);
#pragma unroll
            for (int ks = 0; ks < 4; ++ks) {
                float4 a0 = ab[ks * A_BLK_F4];
                float4 a1 = ab[(4 + ks) * A_BLK_F4];
                const float2* bk = bb + ks * 4 * B_BLK_F2;
#pragma unroll
                for (int j = 0; j < 4; ++j) {
                    float2 b = bk[j * 8];
                    mma_tf32(acc[0][j],
                             __float_as_uint(a0.x), __float_as_uint(a0.y),
                             __float_as_uint(a0.z), __float_as_uint(a0.w),
                             __float_as_uint(b.x), __float_as_uint(b.y));
                    mma_tf32(acc[1][j],
                             __float_as_uint(a1.x), __float_as_uint(a1.y),
                             __float_as_uint(a1.z), __float_as_uint(a1.w),
                             __float_as_uint(b.x), __float_as_uint(b.y));
                }
            }
        }

        if (nt < NT) sts_tile(nt & 1);
        __syncthreads();
    }

    // ---- per-row lin/t reduce (A loaders only; 4 cseg lanes per row pair) ----
    if (isA) {
        linLo += __shfl_xor_sync(0xffffffffu, linLo, 1);
        linLo += __shfl_xor_sync(0xffffffffu, linLo, 2);
        linHi += __shfl_xor_sync(0xffffffffu, linHi, 1);
        linHi += __shfl_xor_sync(0xffffffffu, linHi, 2);
        tLo += __shfl_xor_sync(0xffffffffu, tLo, 1);
        tLo += __shfl_xor_sync(0xffffffffu, tLo, 2);
        tHi += __shfl_xor_sync(0xffffffffu, tHi, 1);
        tHi += __shfl_xor_sync(0xffffffffu, tHi, 2);
        if (cseg == 0) {
            rowLin[rlow] = linLo;  rowT[rlow] = tLo;
            rowLin[rlow + 8] = linHi;  rowT[rlow + 8] = tHi;
        }
    }

    // ---- epilogue: per-warp sum of squares over its 32 cols ----
#pragma unroll
    for (int i = 0; i < 2; ++i) {
        float sLo = 0.f, sHi = 0.f;
#pragma unroll
        for (int j = 0; j < 4; ++j) {
            sLo += acc[i][j][0] * acc[i][j][0] + acc[i][j][1] * acc[i][j][1];
            sHi += acc[i][j][2] * acc[i][j][2] + acc[i][j][3] * acc[i][j][3];
        }
        sLo += __shfl_xor_sync(0xffffffffu, sLo, 1);
        sLo += __shfl_xor_sync(0xffffffffu, sLo, 2);
        sHi += __shfl_xor_sync(0xffffffffu, sHi, 1);
        sHi += __shfl_xor_sync(0xffffffffu, sHi, 2);
        if ((lane & 3) == 0) {
            int rowL = wm * 32 + i * 16 + (lane >> 2);
            pS[rowL * 4 + wn] = sLo;
            pS[(rowL + 8) * 4 + wn] = sHi;
        }
    }
    __syncthreads();

    if (tid < BM) {
        float ssum = pS[tid * 4] + pS[tid * 4 + 1] + pS[tid * 4 + 2] + pS[tid * 4 + 3];
        float cross = 0.5f * (ssum - rowT[tid]) * (1.0f / (float)K_DIM);
        float z = rowLin[tid] + blin[0] + cross;
        out[blockRow + tid] = 1.0f / (1.0f + expf(-z));
    }
}

extern "C" void kernel_launch(void* const* d_in, const int* in_sizes, int n_in,
                              void* d_out, int out_size) {
    const float* x    = (const float*)d_in[0];
    const float* kern = (const float*)d_in[1];
    const float* wlin = (const float*)d_in[2];
    const float* blin = (const float*)d_in[3];
    float* out = (float*)d_out;
    const int B = out_size;

    cudaFuncSetAttribute(fm_mma_kernel,
                         cudaFuncAttributeMaxDynamicSharedMemorySize, SMEM_BYTES);
    prep_kernel<<<64, 256>>>(kern, wlin);
    fm_mma_kernel<<<B / BM, 512, SMEM_BYTES>>>(x, blin, out);
}